// round 13
// baseline (speedup 1.0000x reference)
#include <cuda_runtime.h>
#include <cuda_fp16.h>
#include <math.h>

#define N_NODES 100000
#define N_EDGES 1600000
#define NFEAT 128
#define NHID 64
#define NCLASS 40

#define SCAN_BLK 1024
#define NB ((N_NODES + SCAN_BLK - 1) / SCAN_BLK)   // 98

// ---- scratch (__device__ globals; no allocation allowed) ----
__device__ float g_dinv[N_NODES];
__device__ __align__(256) __half g_Ah[N_NODES * NHID];   // fp16 (X@W) [layer1: unscaled]
__device__ __align__(256) __half g_Ch[N_NODES * NHID];   // fp16 post-activation
__device__ __align__(256) float g_L[N_NODES * NHID];     // logits fp32
__device__ int g_cnt[N_NODES];
__device__ int g_scan[N_NODES];
__device__ int g_bsum[NB];
__device__ int g_rowptr[N_NODES + 1];
__device__ int g_cursor[N_NODES];
__device__ __align__(256) int g_csr[N_EDGES];

// ------------------------------------------------------------ CSR build
__global__ void zero_cnt_kernel() {
    int i = blockIdx.x * blockDim.x + threadIdx.x;
    if (i < N_NODES) g_cnt[i] = 0;
}

__global__ void hist_kernel(const int* __restrict__ dst) {
    int e = blockIdx.x * blockDim.x + threadIdx.x;
    if (e < N_EDGES) atomicAdd(&g_cnt[dst[e]], 1);
}

// scan1: warp-shuffle inclusive scan per 1024-block (also computes dinv)
__global__ void scan1_kernel() {
    __shared__ int warpSums[32];
    int t = threadIdx.x;
    int i = blockIdx.x * SCAN_BLK + t;
    int lane = t & 31;
    int warp = t >> 5;

    int v = (i < N_NODES) ? g_cnt[i] : 0;
    if (i < N_NODES) g_dinv[i] = rsqrtf((float)v + 1.0f);  // +1 self-loop

    int x = v;
#pragma unroll
    for (int off = 1; off < 32; off <<= 1) {
        int y = __shfl_up_sync(0xFFFFFFFFu, x, off);
        if (lane >= off) x += y;
    }
    if (lane == 31) warpSums[warp] = x;
    __syncthreads();

    if (warp == 0) {
        int w = warpSums[lane];
#pragma unroll
        for (int off = 1; off < 32; off <<= 1) {
            int y = __shfl_up_sync(0xFFFFFFFFu, w, off);
            if (lane >= off) w += y;
        }
        warpSums[lane] = w;
    }
    __syncthreads();

    int incl = x + (warp > 0 ? warpSums[warp - 1] : 0);
    if (i < N_NODES) g_scan[i] = incl - v;   // exclusive within block
    if (t == SCAN_BLK - 1) g_bsum[blockIdx.x] = incl;
}

// merged scan2+scan3: every block redundantly scans the NB block sums in smem
__global__ void scan3_kernel() {
    __shared__ int sm[2][128];
    int t = threadIdx.x;
    if (t < 128) sm[0][t] = (t < NB) ? g_bsum[t] : 0;
    __syncthreads();
    int pi = 0;
#pragma unroll
    for (int off = 1; off < 128; off <<= 1) {
        if (t < 128) {
            int x = sm[pi][t];
            if (t >= off) x += sm[pi][t - off];
            sm[pi ^ 1][t] = x;
        }
        __syncthreads();
        pi ^= 1;
    }
    int i = blockIdx.x * blockDim.x + t;
    if (i < N_NODES) {
        int b = i >> 10;
        int base = (b > 0) ? sm[pi][b - 1] : 0;
        int r = g_scan[i] + base;
        g_rowptr[i] = r;
        g_cursor[i] = r;
    }
    if (i == 0) g_rowptr[N_NODES] = N_EDGES;
}

__global__ void fill_kernel(const int* __restrict__ src,
                            const int* __restrict__ dst) {
    int e = blockIdx.x * blockDim.x + threadIdx.x;
    if (e < N_EDGES) {
        int d = dst[e];
        int pos = atomicAdd(&g_cursor[d], 1);
        g_csr[pos] = src[e];
    }
}

// ------------------------------------------------------------- HMMA GEMM
// SCALE=true:  out = dinv[row] * (X@W)   (reads g_dinv in epilogue)
// SCALE=false: out = X@W                 (no dinv dependency at all)
template <int K, int M, int WS_STRIDE, bool CVT_A, bool SCALE, typename XT>
__global__ void __launch_bounds__(256) gemm_mma_kernel(
    const XT* __restrict__ X, const float* __restrict__ W,
    __half* __restrict__ out)
{
    constexpr int AS_STRIDE = K + 8;
    constexpr int NC = M / 8;
    __shared__ __align__(16) __half Asm[128 * AS_STRIDE];
    __shared__ __align__(16) __half Wsm[K * WS_STRIDE];

    const int tid = threadIdx.x;
    const int warp = tid >> 5;
    const int lane = tid & 31;
    const int rowBase = blockIdx.x * 128;

    if (CVT_A) {
        const float4* X4 = reinterpret_cast<const float4*>(X);
        constexpr int SEGS = K / 4;
        for (int idx = tid; idx < 128 * SEGS; idx += 256) {
            int rl = idx / SEGS;
            int seg = idx % SEGS;
            int row = rowBase + rl;
            float4 v = make_float4(0.f, 0.f, 0.f, 0.f);
            if (row < N_NODES) v = __ldg(&X4[(size_t)row * SEGS + seg]);
            __half2 h0 = __float22half2_rn(make_float2(v.x, v.y));
            __half2 h1 = __float22half2_rn(make_float2(v.z, v.w));
            uint2 p;
            p.x = *reinterpret_cast<unsigned*>(&h0);
            p.y = *reinterpret_cast<unsigned*>(&h1);
            *reinterpret_cast<uint2*>(&Asm[rl * AS_STRIDE + seg * 4]) = p;
        }
    } else {
        const uint4* X4 = reinterpret_cast<const uint4*>(X);
        constexpr int SEGS = K / 8;
        for (int idx = tid; idx < 128 * SEGS; idx += 256) {
            int rl = idx / SEGS;
            int seg = idx % SEGS;
            int row = rowBase + rl;
            uint4 v = make_uint4(0u, 0u, 0u, 0u);
            if (row < N_NODES) v = __ldg(&X4[(size_t)row * SEGS + seg]);
            *reinterpret_cast<uint4*>(&Asm[rl * AS_STRIDE + seg * 8]) = v;
        }
    }
    for (int idx = tid; idx < K * M; idx += 256) {
        int k = idx / M;
        int m = idx % M;
        Wsm[k * WS_STRIDE + m] = __float2half(__ldg(&W[idx]));
    }
    __syncthreads();

    float acc[NC][4];
#pragma unroll
    for (int n = 0; n < NC; n++)
#pragma unroll
        for (int q = 0; q < 4; q++) acc[n][q] = 0.f;

    const unsigned aBase = (unsigned)__cvta_generic_to_shared(Asm);
    const unsigned wBase = (unsigned)__cvta_generic_to_shared(Wsm);
    const int rlane = lane & 15;
    const int hilo = lane >> 4;

#pragma unroll
    for (int k0 = 0; k0 < K; k0 += 16) {
        unsigned a0, a1, a2, a3;
        unsigned aAddr = aBase +
            ((warp * 16 + rlane) * AS_STRIDE + k0) * 2 + hilo * 16;
        asm volatile("ldmatrix.sync.aligned.m8n8.x4.shared.b16 {%0,%1,%2,%3}, [%4];"
                     : "=r"(a0), "=r"(a1), "=r"(a2), "=r"(a3) : "r"(aAddr));
#pragma unroll
        for (int n = 0; n < NC; n++) {
            unsigned b0, b1;
            unsigned bAddr = wBase + ((k0 + rlane) * WS_STRIDE + n * 8) * 2;
            asm volatile("ldmatrix.sync.aligned.m8n8.x2.trans.shared.b16 {%0,%1}, [%2];"
                         : "=r"(b0), "=r"(b1) : "r"(bAddr));
            asm volatile(
                "mma.sync.aligned.m16n8k16.row.col.f32.f16.f16.f32 "
                "{%0,%1,%2,%3}, {%4,%5,%6,%7}, {%8,%9}, {%0,%1,%2,%3};"
                : "+f"(acc[n][0]), "+f"(acc[n][1]), "+f"(acc[n][2]), "+f"(acc[n][3])
                : "r"(a0), "r"(a1), "r"(a2), "r"(a3), "r"(b0), "r"(b1));
        }
    }

    int row0 = rowBase + warp * 16 + (lane >> 2);
    int row1 = row0 + 8;
    float s0 = 1.f, s1 = 1.f;
    if (SCALE) {
        s0 = (row0 < N_NODES) ? g_dinv[row0] : 0.f;
        s1 = (row1 < N_NODES) ? g_dinv[row1] : 0.f;
    }
    unsigned* outU = reinterpret_cast<unsigned*>(out);
#pragma unroll
    for (int n = 0; n < NC; n++) {
        int col = n * 8 + (lane & 3) * 2;
        if (row0 < N_NODES) {
            __half2 h = __float22half2_rn(make_float2(acc[n][0] * s0, acc[n][1] * s0));
            outU[((size_t)row0 * M + col) >> 1] = *reinterpret_cast<unsigned*>(&h);
        }
        if (row1 < N_NODES) {
            __half2 h = __float22half2_rn(make_float2(acc[n][2] * s1, acc[n][3] * s1));
            outU[((size_t)row1 * M + col) >> 1] = *reinterpret_cast<unsigned*>(&h);
        }
    }
}

// ------------------------------------------------------- fused gather
struct F8 { float v[8]; };
__device__ __forceinline__ void acc8(F8& a, uint4 p) {
    const __half2* h = reinterpret_cast<const __half2*>(&p);
#pragma unroll
    for (int q = 0; q < 4; q++) {
        float2 f = __half22float2(h[q]);
        a.v[2 * q]     += f.x;
        a.v[2 * q + 1] += f.y;
    }
}
__device__ __forceinline__ void acc8s(F8& a, uint4 p, float s) {
    const __half2* h = reinterpret_cast<const __half2*>(&p);
#pragma unroll
    for (int q = 0; q < 4; q++) {
        float2 f = __half22float2(h[q]);
        a.v[2 * q]     = fmaf(s, f.x, a.v[2 * q]);
        a.v[2 * q + 1] = fmaf(s, f.y, a.v[2 * q + 1]);
    }
}

// SRC_SCALED=false: g holds unscaled XW; scale each source row by dinv[src].
// 8 threads/row, 8 features/thread, 4 independent accumulation chains.
template <bool SRC_SCALED>
__global__ void __launch_bounds__(512) gather_relu64_kernel(
    const uint4* __restrict__ g, const float* __restrict__ bias,
    uint4* __restrict__ Ch)
{
    int tid = blockIdx.x * blockDim.x + threadIdx.x;
    int row = tid >> 3;
    int j = tid & 7;
    if (row >= N_NODES) return;
    int beg = g_rowptr[row], end = g_rowptr[row + 1];

    F8 a0, a1, a2, a3;
#pragma unroll
    for (int q = 0; q < 8; q++) { a0.v[q] = 0.f; a1.v[q] = 0.f; a2.v[q] = 0.f; a3.v[q] = 0.f; }

    int e = beg;
    for (; e + 3 < end; e += 4) {
        int s0 = __ldg(&g_csr[e]);
        int s1 = __ldg(&g_csr[e + 1]);
        int s2 = __ldg(&g_csr[e + 2]);
        int s3 = __ldg(&g_csr[e + 3]);
        uint4 p0 = __ldg(&g[(size_t)s0 * 8 + j]);
        uint4 p1 = __ldg(&g[(size_t)s1 * 8 + j]);
        uint4 p2 = __ldg(&g[(size_t)s2 * 8 + j]);
        uint4 p3 = __ldg(&g[(size_t)s3 * 8 + j]);
        if (SRC_SCALED) {
            acc8(a0, p0); acc8(a1, p1); acc8(a2, p2); acc8(a3, p3);
        } else {
            acc8s(a0, p0, __ldg(&g_dinv[s0]));
            acc8s(a1, p1, __ldg(&g_dinv[s1]));
            acc8s(a2, p2, __ldg(&g_dinv[s2]));
            acc8s(a3, p3, __ldg(&g_dinv[s3]));
        }
    }
    for (; e < end; e++) {
        int s = __ldg(&g_csr[e]);
        if (SRC_SCALED) acc8(a0, __ldg(&g[(size_t)s * 8 + j]));
        else            acc8s(a0, __ldg(&g[(size_t)s * 8 + j]), __ldg(&g_dinv[s]));
    }
    float sr = g_dinv[row];
    if (SRC_SCALED) acc8(a1, __ldg(&g[(size_t)row * 8 + j]));       // self
    else            acc8s(a1, __ldg(&g[(size_t)row * 8 + j]), sr);  // self
#pragma unroll
    for (int q = 0; q < 8; q++) a0.v[q] = (a0.v[q] + a1.v[q]) + (a2.v[q] + a3.v[q]);

    const float4* b4 = reinterpret_cast<const float4*>(bias);
    float4 bb0 = __ldg(&b4[2 * j]);
    float4 bb1 = __ldg(&b4[2 * j + 1]);
    float r0 = fmaxf(fmaf(sr, a0.v[0], bb0.x), 0.f);
    float r1 = fmaxf(fmaf(sr, a0.v[1], bb0.y), 0.f);
    float r2 = fmaxf(fmaf(sr, a0.v[2], bb0.z), 0.f);
    float r3 = fmaxf(fmaf(sr, a0.v[3], bb0.w), 0.f);
    float r4 = fmaxf(fmaf(sr, a0.v[4], bb1.x), 0.f);
    float r5 = fmaxf(fmaf(sr, a0.v[5], bb1.y), 0.f);
    float r6 = fmaxf(fmaf(sr, a0.v[6], bb1.z), 0.f);
    float r7 = fmaxf(fmaf(sr, a0.v[7], bb1.w), 0.f);
    __half2 h0 = __float22half2_rn(make_float2(r0, r1));
    __half2 h1 = __float22half2_rn(make_float2(r2, r3));
    __half2 h2 = __float22half2_rn(make_float2(r4, r5));
    __half2 h3 = __float22half2_rn(make_float2(r6, r7));
    uint4 o;
    o.x = *reinterpret_cast<unsigned*>(&h0);
    o.y = *reinterpret_cast<unsigned*>(&h1);
    o.z = *reinterpret_cast<unsigned*>(&h2);
    o.w = *reinterpret_cast<unsigned*>(&h3);
    Ch[(size_t)row * 8 + j] = o;
}

// L[row] = dinv[row]*(sum g40[src_e] + g40[row]) + b3 (fp32 out).
// 10 threads/row, 4 features (8B) per thread, 2 chains.
__global__ void __launch_bounds__(512) gather_logits40_kernel(
    const uint2* __restrict__ g, const float* __restrict__ b3,
    float4* __restrict__ L)
{
    int tid = blockIdx.x * blockDim.x + threadIdx.x;
    int row = tid / 10;
    int j = tid - row * 10;
    if (row >= N_NODES) return;
    int beg = g_rowptr[row], end = g_rowptr[row + 1];

    float a0 = 0.f, a1 = 0.f, a2 = 0.f, a3 = 0.f;
    float c0 = 0.f, c1 = 0.f, c2 = 0.f, c3 = 0.f;
    int e = beg;
    for (; e + 1 < end; e += 2) {
        int s0 = __ldg(&g_csr[e]);
        int s1 = __ldg(&g_csr[e + 1]);
        uint2 p = __ldg(&g[(size_t)s0 * 10 + j]);
        uint2 q = __ldg(&g[(size_t)s1 * 10 + j]);
        float2 f0 = __half22float2(*reinterpret_cast<const __half2*>(&p.x));
        float2 f1 = __half22float2(*reinterpret_cast<const __half2*>(&p.y));
        float2 g0 = __half22float2(*reinterpret_cast<const __half2*>(&q.x));
        float2 g1 = __half22float2(*reinterpret_cast<const __half2*>(&q.y));
        a0 += f0.x; a1 += f0.y; a2 += f1.x; a3 += f1.y;
        c0 += g0.x; c1 += g0.y; c2 += g1.x; c3 += g1.y;
    }
    if (e < end) {
        int s = __ldg(&g_csr[e]);
        uint2 p = __ldg(&g[(size_t)s * 10 + j]);
        float2 f0 = __half22float2(*reinterpret_cast<const __half2*>(&p.x));
        float2 f1 = __half22float2(*reinterpret_cast<const __half2*>(&p.y));
        a0 += f0.x; a1 += f0.y; a2 += f1.x; a3 += f1.y;
    }
    {
        uint2 p = __ldg(&g[(size_t)row * 10 + j]);   // self loop
        float2 f0 = __half22float2(*reinterpret_cast<const __half2*>(&p.x));
        float2 f1 = __half22float2(*reinterpret_cast<const __half2*>(&p.y));
        a0 += f0.x; a1 += f0.y; a2 += f1.x; a3 += f1.y;
    }
    a0 += c0; a1 += c1; a2 += c2; a3 += c3;
    float s = g_dinv[row];
    float4 bb = __ldg(&reinterpret_cast<const float4*>(b3)[j]);
    float4 r;
    r.x = fmaf(s, a0, bb.x);
    r.y = fmaf(s, a1, bb.y);
    r.z = fmaf(s, a2, bb.z);
    r.w = fmaf(s, a3, bb.w);
    L[(size_t)row * 10 + j] = r;
}

// --------------------------------------------- final log_softmax (warp/row)
__global__ void final_lsm_kernel(const float* __restrict__ L,
                                 float* __restrict__ out)
{
    int warp = (blockIdx.x * blockDim.x + threadIdx.x) >> 5;
    int lane = threadIdx.x & 31;
    if (warp >= N_NODES) return;
    size_t base = (size_t)warp * 40;

    float v0 = L[base + lane];
    float v1 = (lane < 8) ? L[base + 32 + lane] : -1e30f;

    float m = fmaxf(v0, v1);
#pragma unroll
    for (int off = 16; off > 0; off >>= 1)
        m = fmaxf(m, __shfl_xor_sync(0xFFFFFFFFu, m, off));

    float e = __expf(v0 - m) + ((lane < 8) ? __expf(v1 - m) : 0.f);
#pragma unroll
    for (int off = 16; off > 0; off >>= 1)
        e += __shfl_xor_sync(0xFFFFFFFFu, e, off);

    float ls = __logf(e);
    out[base + lane] = v0 - m - ls;
    if (lane < 8) out[base + 32 + lane] = v1 - m - ls;
}

// ------------------------------------------------------------------ launch
extern "C" void kernel_launch(void* const* d_in, const int* in_sizes, int n_in,
                              void* d_out, int out_size)
{
    const float* x   = (const float*)d_in[0];
    const int* ei    = (const int*)d_in[1];
    const float* W1  = (const float*)d_in[2];
    const float* b1  = (const float*)d_in[3];
    const float* W2  = (const float*)d_in[4];
    const float* b2  = (const float*)d_in[5];
    const float* W3  = (const float*)d_in[6];
    const float* b3  = (const float*)d_in[7];
    float* out       = (float*)d_out;

    const int* src = ei;
    const int* dst = ei + N_EDGES;

    __half* Ah; cudaGetSymbolAddress((void**)&Ah, g_Ah);
    __half* Ch; cudaGetSymbolAddress((void**)&Ch, g_Ch);
    float* L;   cudaGetSymbolAddress((void**)&L, g_L);

    const int TPB = 256;
    const int nodeBlocks = (N_NODES + TPB - 1) / TPB;
    const int edgeBlocks = (N_EDGES + TPB - 1) / TPB;
    const int mma_blocks = (N_NODES + 127) / 128;
    const int g64_blocks = (N_NODES * 8 + 511) / 512;
    const int g40_blocks = (N_NODES * 10 + 511) / 512;

    cudaStream_t s2;
    cudaStreamCreateWithFlags(&s2, cudaStreamNonBlocking);
    cudaEvent_t evA, evB;
    cudaEventCreateWithFlags(&evA, cudaEventDisableTiming);
    cudaEventCreateWithFlags(&evB, cudaEventDisableTiming);

    // fork at t=0: gemm1 (unscaled) depends only on x, W1
    cudaEventRecord(evA, 0);
    cudaStreamWaitEvent(s2, evA, 0);
    gemm_mma_kernel<NFEAT, NHID, NHID + 8, true, false>
        <<<mma_blocks, 256, 0, s2>>>(x, W1, Ah);

    // main stream: entire CSR build, concurrent with gemm1
    zero_cnt_kernel<<<nodeBlocks, TPB>>>();
    hist_kernel<<<edgeBlocks, TPB>>>(dst);
    scan1_kernel<<<NB, SCAN_BLK>>>();          // also produces dinv
    scan3_kernel<<<nodeBlocks, TPB>>>();
    fill_kernel<<<edgeBlocks, TPB>>>(src, dst);

    // join: gather1 needs CSR + dinv + gemm1 output
    cudaEventRecord(evB, s2);
    cudaStreamWaitEvent(0, evB, 0);

    // ---- layer 1 aggregation (applies dinv[src] on the fly) ----
    gather_relu64_kernel<false><<<g64_blocks, 512>>>((const uint4*)Ah, b1, (uint4*)Ch);

    // ---- layer 2 ----
    gemm_mma_kernel<NHID, NHID, NHID + 8, false, true><<<mma_blocks, 256>>>(Ch, W2, Ah);
    gather_relu64_kernel<true><<<g64_blocks, 512>>>((const uint4*)Ah, b2, (uint4*)Ch);

    // ---- layer 3 ----
    gemm_mma_kernel<NHID, NCLASS, NCLASS + 16, false, true><<<mma_blocks, 256>>>(Ch, W3, Ah);
    gather_logits40_kernel<<<g40_blocks, 512>>>((const uint2*)Ah, b3, (float4*)L);
    final_lsm_kernel<<<(N_NODES * 32 + TPB - 1) / TPB, TPB>>>(L, out);
}

// round 14
// speedup vs baseline: 1.1608x; 1.1608x over previous
#include <cuda_runtime.h>
#include <cuda_fp16.h>
#include <math.h>

#define N_NODES 100000
#define N_EDGES 1600000
#define NFEAT 128
#define NHID 64
#define NCLASS 40

#define SCAN_BLK 1024
#define NB ((N_NODES + SCAN_BLK - 1) / SCAN_BLK)   // 98

// ---- scratch (__device__ globals; no allocation allowed) ----
// g_cnt starts zero-initialized (fresh CUDA module); every kernel_launch
// invocation re-zeroes it in final_lsm_kernel, so all calls see identical state.
__device__ float g_dinv[N_NODES];
__device__ __align__(16) __half g_Ah[N_NODES * NHID];   // fp16 (X@W) [layer1: unscaled]
__device__ __align__(16) __half g_Ch[N_NODES * NHID];   // fp16 post-activation
__device__ __align__(16) float g_L[N_NODES * NHID];     // logits fp32
__device__ int g_cnt[N_NODES];
__device__ int g_scan[N_NODES];
__device__ int g_bsum[NB];
__device__ int g_rowptr[N_NODES + 1];
__device__ int g_cursor[N_NODES];
__device__ int g_csr[N_EDGES];

// ------------------------------------------------------------ CSR build
__global__ void hist_kernel(const int* __restrict__ dst) {
    int e = blockIdx.x * blockDim.x + threadIdx.x;
    if (e < N_EDGES) atomicAdd(&g_cnt[dst[e]], 1);
}

// scan1: warp-shuffle inclusive scan per 1024-block (also computes dinv)
__global__ void scan1_kernel() {
    __shared__ int warpSums[32];
    int t = threadIdx.x;
    int i = blockIdx.x * SCAN_BLK + t;
    int lane = t & 31;
    int warp = t >> 5;

    int v = (i < N_NODES) ? g_cnt[i] : 0;
    if (i < N_NODES) g_dinv[i] = rsqrtf((float)v + 1.0f);  // +1 self-loop

    int x = v;
#pragma unroll
    for (int off = 1; off < 32; off <<= 1) {
        int y = __shfl_up_sync(0xFFFFFFFFu, x, off);
        if (lane >= off) x += y;
    }
    if (lane == 31) warpSums[warp] = x;
    __syncthreads();

    if (warp == 0) {
        int w = warpSums[lane];
#pragma unroll
        for (int off = 1; off < 32; off <<= 1) {
            int y = __shfl_up_sync(0xFFFFFFFFu, w, off);
            if (lane >= off) w += y;
        }
        warpSums[lane] = w;
    }
    __syncthreads();

    int incl = x + (warp > 0 ? warpSums[warp - 1] : 0);
    if (i < N_NODES) g_scan[i] = incl - v;   // exclusive within block
    if (t == SCAN_BLK - 1) g_bsum[blockIdx.x] = incl;
}

// merged scan2+scan3: every block redundantly scans the NB block sums in smem
__global__ void scan3_kernel() {
    __shared__ int sm[2][128];
    int t = threadIdx.x;
    if (t < 128) sm[0][t] = (t < NB) ? g_bsum[t] : 0;
    __syncthreads();
    int pi = 0;
#pragma unroll
    for (int off = 1; off < 128; off <<= 1) {
        if (t < 128) {
            int x = sm[pi][t];
            if (t >= off) x += sm[pi][t - off];
            sm[pi ^ 1][t] = x;
        }
        __syncthreads();
        pi ^= 1;
    }
    int i = blockIdx.x * blockDim.x + t;
    if (i < N_NODES) {
        int b = i >> 10;
        int base = (b > 0) ? sm[pi][b - 1] : 0;
        int r = g_scan[i] + base;
        g_rowptr[i] = r;
        g_cursor[i] = r;
    }
    if (i == 0) g_rowptr[N_NODES] = N_EDGES;
}

__global__ void fill_kernel(const int* __restrict__ src,
                            const int* __restrict__ dst) {
    int e = blockIdx.x * blockDim.x + threadIdx.x;
    if (e < N_EDGES) {
        int d = dst[e];
        int pos = atomicAdd(&g_cursor[d], 1);
        g_csr[pos] = src[e];
    }
}

// ------------------------------------------------------------- HMMA GEMM
// SCALE=true:  out = dinv[row] * (X@W)   (reads g_dinv in epilogue)
// SCALE=false: out = X@W                 (no dinv dependency at all)
template <int K, int M, int WS_STRIDE, bool CVT_A, bool SCALE, typename XT>
__global__ void __launch_bounds__(256) gemm_mma_kernel(
    const XT* __restrict__ X, const float* __restrict__ W,
    __half* __restrict__ out)
{
    constexpr int AS_STRIDE = K + 8;
    constexpr int NC = M / 8;
    __shared__ __align__(16) __half Asm[128 * AS_STRIDE];
    __shared__ __align__(16) __half Wsm[K * WS_STRIDE];

    const int tid = threadIdx.x;
    const int warp = tid >> 5;
    const int lane = tid & 31;
    const int rowBase = blockIdx.x * 128;

    if (CVT_A) {
        const float4* X4 = reinterpret_cast<const float4*>(X);
        constexpr int SEGS = K / 4;
        for (int idx = tid; idx < 128 * SEGS; idx += 256) {
            int rl = idx / SEGS;
            int seg = idx % SEGS;
            int row = rowBase + rl;
            float4 v = make_float4(0.f, 0.f, 0.f, 0.f);
            if (row < N_NODES) v = __ldg(&X4[(size_t)row * SEGS + seg]);
            __half2 h0 = __float22half2_rn(make_float2(v.x, v.y));
            __half2 h1 = __float22half2_rn(make_float2(v.z, v.w));
            uint2 p;
            p.x = *reinterpret_cast<unsigned*>(&h0);
            p.y = *reinterpret_cast<unsigned*>(&h1);
            *reinterpret_cast<uint2*>(&Asm[rl * AS_STRIDE + seg * 4]) = p;
        }
    } else {
        const uint4* X4 = reinterpret_cast<const uint4*>(X);
        constexpr int SEGS = K / 8;
        for (int idx = tid; idx < 128 * SEGS; idx += 256) {
            int rl = idx / SEGS;
            int seg = idx % SEGS;
            int row = rowBase + rl;
            uint4 v = make_uint4(0u, 0u, 0u, 0u);
            if (row < N_NODES) v = __ldg(&X4[(size_t)row * SEGS + seg]);
            *reinterpret_cast<uint4*>(&Asm[rl * AS_STRIDE + seg * 8]) = v;
        }
    }
    for (int idx = tid; idx < K * M; idx += 256) {
        int k = idx / M;
        int m = idx % M;
        Wsm[k * WS_STRIDE + m] = __float2half(__ldg(&W[idx]));
    }
    __syncthreads();

    float acc[NC][4];
#pragma unroll
    for (int n = 0; n < NC; n++)
#pragma unroll
        for (int q = 0; q < 4; q++) acc[n][q] = 0.f;

    const unsigned aBase = (unsigned)__cvta_generic_to_shared(Asm);
    const unsigned wBase = (unsigned)__cvta_generic_to_shared(Wsm);
    const int rlane = lane & 15;
    const int hilo = lane >> 4;

#pragma unroll
    for (int k0 = 0; k0 < K; k0 += 16) {
        unsigned a0, a1, a2, a3;
        unsigned aAddr = aBase +
            ((warp * 16 + rlane) * AS_STRIDE + k0) * 2 + hilo * 16;
        asm volatile("ldmatrix.sync.aligned.m8n8.x4.shared.b16 {%0,%1,%2,%3}, [%4];"
                     : "=r"(a0), "=r"(a1), "=r"(a2), "=r"(a3) : "r"(aAddr));
#pragma unroll
        for (int n = 0; n < NC; n++) {
            unsigned b0, b1;
            unsigned bAddr = wBase + ((k0 + rlane) * WS_STRIDE + n * 8) * 2;
            asm volatile("ldmatrix.sync.aligned.m8n8.x2.trans.shared.b16 {%0,%1}, [%2];"
                         : "=r"(b0), "=r"(b1) : "r"(bAddr));
            asm volatile(
                "mma.sync.aligned.m16n8k16.row.col.f32.f16.f16.f32 "
                "{%0,%1,%2,%3}, {%4,%5,%6,%7}, {%8,%9}, {%0,%1,%2,%3};"
                : "+f"(acc[n][0]), "+f"(acc[n][1]), "+f"(acc[n][2]), "+f"(acc[n][3])
                : "r"(a0), "r"(a1), "r"(a2), "r"(a3), "r"(b0), "r"(b1));
        }
    }

    int row0 = rowBase + warp * 16 + (lane >> 2);
    int row1 = row0 + 8;
    float s0 = 1.f, s1 = 1.f;
    if (SCALE) {
        s0 = (row0 < N_NODES) ? g_dinv[row0] : 0.f;
        s1 = (row1 < N_NODES) ? g_dinv[row1] : 0.f;
    }
    unsigned* outU = reinterpret_cast<unsigned*>(out);
#pragma unroll
    for (int n = 0; n < NC; n++) {
        int col = n * 8 + (lane & 3) * 2;
        if (row0 < N_NODES) {
            __half2 h = __float22half2_rn(make_float2(acc[n][0] * s0, acc[n][1] * s0));
            outU[((size_t)row0 * M + col) >> 1] = *reinterpret_cast<unsigned*>(&h);
        }
        if (row1 < N_NODES) {
            __half2 h = __float22half2_rn(make_float2(acc[n][2] * s1, acc[n][3] * s1));
            outU[((size_t)row1 * M + col) >> 1] = *reinterpret_cast<unsigned*>(&h);
        }
    }
}

// ------------------------------------------------------- fused gather
struct F8 { float v[8]; };
__device__ __forceinline__ void acc8(F8& a, uint4 p) {
    const __half2* h = reinterpret_cast<const __half2*>(&p);
#pragma unroll
    for (int q = 0; q < 4; q++) {
        float2 f = __half22float2(h[q]);
        a.v[2 * q]     += f.x;
        a.v[2 * q + 1] += f.y;
    }
}
__device__ __forceinline__ void acc8s(F8& a, uint4 p, float s) {
    const __half2* h = reinterpret_cast<const __half2*>(&p);
#pragma unroll
    for (int q = 0; q < 4; q++) {
        float2 f = __half22float2(h[q]);
        a.v[2 * q]     = fmaf(s, f.x, a.v[2 * q]);
        a.v[2 * q + 1] = fmaf(s, f.y, a.v[2 * q + 1]);
    }
}

// SRC_SCALED=false: g holds unscaled XW; scale each source row by dinv[src].
// 8 threads/row, 8 features/thread, 2 chains (R12-proven shape).
template <bool SRC_SCALED>
__global__ void gather_relu64_kernel(const uint4* __restrict__ g,
                                     const float* __restrict__ bias,
                                     uint4* __restrict__ Ch)
{
    int tid = blockIdx.x * blockDim.x + threadIdx.x;
    int row = tid >> 3;
    int j = tid & 7;
    if (row >= N_NODES) return;
    int beg = g_rowptr[row], end = g_rowptr[row + 1];

    F8 a0, a1;
#pragma unroll
    for (int q = 0; q < 8; q++) { a0.v[q] = 0.f; a1.v[q] = 0.f; }

    int e = beg;
    for (; e + 1 < end; e += 2) {
        int s0 = __ldg(&g_csr[e]);
        int s1 = __ldg(&g_csr[e + 1]);
        if (SRC_SCALED) {
            acc8(a0, __ldg(&g[(size_t)s0 * 8 + j]));
            acc8(a1, __ldg(&g[(size_t)s1 * 8 + j]));
        } else {
            float d0 = __ldg(&g_dinv[s0]);
            float d1 = __ldg(&g_dinv[s1]);
            acc8s(a0, __ldg(&g[(size_t)s0 * 8 + j]), d0);
            acc8s(a1, __ldg(&g[(size_t)s1 * 8 + j]), d1);
        }
    }
    if (e < end) {
        int s = __ldg(&g_csr[e]);
        if (SRC_SCALED) acc8(a0, __ldg(&g[(size_t)s * 8 + j]));
        else            acc8s(a0, __ldg(&g[(size_t)s * 8 + j]), __ldg(&g_dinv[s]));
    }
    float sr = g_dinv[row];
    if (SRC_SCALED) acc8(a0, __ldg(&g[(size_t)row * 8 + j]));       // self
    else            acc8s(a0, __ldg(&g[(size_t)row * 8 + j]), sr);  // self
#pragma unroll
    for (int q = 0; q < 8; q++) a0.v[q] += a1.v[q];

    const float4* b4 = reinterpret_cast<const float4*>(bias);
    float4 bb0 = __ldg(&b4[2 * j]);
    float4 bb1 = __ldg(&b4[2 * j + 1]);
    float r0 = fmaxf(fmaf(sr, a0.v[0], bb0.x), 0.f);
    float r1 = fmaxf(fmaf(sr, a0.v[1], bb0.y), 0.f);
    float r2 = fmaxf(fmaf(sr, a0.v[2], bb0.z), 0.f);
    float r3 = fmaxf(fmaf(sr, a0.v[3], bb0.w), 0.f);
    float r4 = fmaxf(fmaf(sr, a0.v[4], bb1.x), 0.f);
    float r5 = fmaxf(fmaf(sr, a0.v[5], bb1.y), 0.f);
    float r6 = fmaxf(fmaf(sr, a0.v[6], bb1.z), 0.f);
    float r7 = fmaxf(fmaf(sr, a0.v[7], bb1.w), 0.f);
    __half2 h0 = __float22half2_rn(make_float2(r0, r1));
    __half2 h1 = __float22half2_rn(make_float2(r2, r3));
    __half2 h2 = __float22half2_rn(make_float2(r4, r5));
    __half2 h3 = __float22half2_rn(make_float2(r6, r7));
    uint4 o;
    o.x = *reinterpret_cast<unsigned*>(&h0);
    o.y = *reinterpret_cast<unsigned*>(&h1);
    o.z = *reinterpret_cast<unsigned*>(&h2);
    o.w = *reinterpret_cast<unsigned*>(&h3);
    Ch[(size_t)row * 8 + j] = o;
}

// L[row] = dinv[row]*(sum g40[src_e] + g40[row]) + b3 (fp32 out).
// 10 threads/row, 4 features (8B) per thread (R12-proven shape).
__global__ void gather_logits40_kernel(const uint2* __restrict__ g,
                                       const float* __restrict__ b3,
                                       float4* __restrict__ L)
{
    int tid = blockIdx.x * blockDim.x + threadIdx.x;
    int row = tid / 10;
    int j = tid - row * 10;
    if (row >= N_NODES) return;
    int beg = g_rowptr[row], end = g_rowptr[row + 1];

    float a0 = 0.f, a1 = 0.f, a2 = 0.f, a3 = 0.f;
    for (int e = beg; e < end; e++) {
        int s = __ldg(&g_csr[e]);
        uint2 p = __ldg(&g[(size_t)s * 10 + j]);
        float2 f0 = __half22float2(*reinterpret_cast<const __half2*>(&p.x));
        float2 f1 = __half22float2(*reinterpret_cast<const __half2*>(&p.y));
        a0 += f0.x; a1 += f0.y; a2 += f1.x; a3 += f1.y;
    }
    {
        uint2 p = __ldg(&g[(size_t)row * 10 + j]);   // self loop
        float2 f0 = __half22float2(*reinterpret_cast<const __half2*>(&p.x));
        float2 f1 = __half22float2(*reinterpret_cast<const __half2*>(&p.y));
        a0 += f0.x; a1 += f0.y; a2 += f1.x; a3 += f1.y;
    }
    float s = g_dinv[row];
    float4 bb = __ldg(&reinterpret_cast<const float4*>(b3)[j]);
    float4 r;
    r.x = fmaf(s, a0, bb.x);
    r.y = fmaf(s, a1, bb.y);
    r.z = fmaf(s, a2, bb.z);
    r.w = fmaf(s, a3, bb.w);
    L[(size_t)row * 10 + j] = r;
}

// ---------------- final log_softmax (warp/row) + g_cnt re-zero ----------
__global__ void final_lsm_kernel(const float* __restrict__ L,
                                 float* __restrict__ out)
{
    int gtid = blockIdx.x * blockDim.x + threadIdx.x;
    // re-zero g_cnt for the next invocation (grid has 3.2M threads)
    if (gtid < N_NODES) g_cnt[gtid] = 0;

    int warp = gtid >> 5;
    int lane = threadIdx.x & 31;
    if (warp >= N_NODES) return;
    size_t base = (size_t)warp * 40;

    float v0 = L[base + lane];
    float v1 = (lane < 8) ? L[base + 32 + lane] : -1e30f;

    float m = fmaxf(v0, v1);
#pragma unroll
    for (int off = 16; off > 0; off >>= 1)
        m = fmaxf(m, __shfl_xor_sync(0xFFFFFFFFu, m, off));

    float e = __expf(v0 - m) + ((lane < 8) ? __expf(v1 - m) : 0.f);
#pragma unroll
    for (int off = 16; off > 0; off >>= 1)
        e += __shfl_xor_sync(0xFFFFFFFFu, e, off);

    float ls = __logf(e);
    out[base + lane] = v0 - m - ls;
    if (lane < 8) out[base + 32 + lane] = v1 - m - ls;
}

// ------------------------------------------------------------------ launch
extern "C" void kernel_launch(void* const* d_in, const int* in_sizes, int n_in,
                              void* d_out, int out_size)
{
    const float* x   = (const float*)d_in[0];
    const int* ei    = (const int*)d_in[1];
    const float* W1  = (const float*)d_in[2];
    const float* b1  = (const float*)d_in[3];
    const float* W2  = (const float*)d_in[4];
    const float* b2  = (const float*)d_in[5];
    const float* W3  = (const float*)d_in[6];
    const float* b3  = (const float*)d_in[7];
    float* out       = (float*)d_out;

    const int* src = ei;
    const int* dst = ei + N_EDGES;

    __half* Ah; cudaGetSymbolAddress((void**)&Ah, g_Ah);
    __half* Ch; cudaGetSymbolAddress((void**)&Ch, g_Ch);
    float* L;   cudaGetSymbolAddress((void**)&L, g_L);

    const int TPB = 256;
    const int nodeBlocks = (N_NODES + TPB - 1) / TPB;
    const int edgeBlocks = (N_EDGES + TPB - 1) / TPB;
    const int mma_blocks = (N_NODES + 127) / 128;
    const int g64_blocks = (N_NODES * 8 + TPB - 1) / TPB;
    const int g40_blocks = (N_NODES * 10 + TPB - 1) / TPB;

    cudaStream_t s2;
    cudaStreamCreateWithFlags(&s2, cudaStreamNonBlocking);
    cudaEvent_t evA, evB;
    cudaEventCreateWithFlags(&evA, cudaEventDisableTiming);
    cudaEventCreateWithFlags(&evB, cudaEventDisableTiming);

    // fork at t=0: gemm1 (unscaled) depends only on x, W1
    cudaEventRecord(evA, 0);
    cudaStreamWaitEvent(s2, evA, 0);
    gemm_mma_kernel<NFEAT, NHID, NHID + 8, true, false>
        <<<mma_blocks, 256, 0, s2>>>(x, W1, Ah);

    // main stream: entire CSR build, concurrent with gemm1
    // (g_cnt was zeroed by the previous invocation's final_lsm_kernel,
    //  or is zero-initialized on the very first call)
    hist_kernel<<<edgeBlocks, TPB>>>(dst);
    scan1_kernel<<<NB, SCAN_BLK>>>();          // also produces dinv
    scan3_kernel<<<nodeBlocks, TPB>>>();
    fill_kernel<<<edgeBlocks, TPB>>>(src, dst);

    // join: gather1 needs CSR + dinv + gemm1 output
    cudaEventRecord(evB, s2);
    cudaStreamWaitEvent(0, evB, 0);

    // ---- layer 1 aggregation (applies dinv[src] on the fly) ----
    gather_relu64_kernel<false><<<g64_blocks, TPB>>>((const uint4*)Ah, b1, (uint4*)Ch);

    // ---- layer 2 ----
    gemm_mma_kernel<NHID, NHID, NHID + 8, false, true><<<mma_blocks, 256>>>(Ch, W2, Ah);
    gather_relu64_kernel<true><<<g64_blocks, TPB>>>((const uint4*)Ah, b2, (uint4*)Ch);

    // ---- layer 3 ----
    gemm_mma_kernel<NHID, NCLASS, NCLASS + 16, false, true><<<mma_blocks, 256>>>(Ch, W3, Ah);
    gather_logits40_kernel<<<g40_blocks, TPB>>>((const uint2*)Ah, b3, (float4*)L);
    final_lsm_kernel<<<(N_NODES * 32 + TPB - 1) / TPB, TPB>>>(L, out);
}

// round 15
// speedup vs baseline: 1.2367x; 1.0653x over previous
#include <cuda_runtime.h>
#include <cuda_fp16.h>
#include <math.h>

#define N_NODES 100000
#define N_EDGES 1600000
#define NFEAT 128
#define NHID 64
#define NCLASS 40

#define SCAN_BLK 1024
#define NB ((N_NODES + SCAN_BLK - 1) / SCAN_BLK)   // 98

// ---- scratch (__device__ globals; no allocation allowed) ----
// g_cnt starts zero-initialized; every invocation re-zeroes it in the final
// fused gather+lsm kernel, so all calls see identical state.
__device__ float g_dinv[N_NODES];
__device__ __align__(16) __half g_Ah[N_NODES * NHID];   // fp16 (X@W) [layer1: unscaled]
__device__ __align__(16) __half g_Ch[N_NODES * NHID];   // fp16 post-activation
__device__ int g_cnt[N_NODES];
__device__ int g_scan[N_NODES];
__device__ int g_bsum[NB];
__device__ int g_rowptr[N_NODES + 1];
__device__ int g_cursor[N_NODES];
__device__ int g_csr[N_EDGES];

// ------------------------------------------------------------ CSR build
__global__ void hist_kernel(const int* __restrict__ dst) {
    int e = blockIdx.x * blockDim.x + threadIdx.x;
    if (e < N_EDGES) atomicAdd(&g_cnt[dst[e]], 1);
}

// scan1: warp-shuffle inclusive scan per 1024-block (also computes dinv)
__global__ void scan1_kernel() {
    __shared__ int warpSums[32];
    int t = threadIdx.x;
    int i = blockIdx.x * SCAN_BLK + t;
    int lane = t & 31;
    int warp = t >> 5;

    int v = (i < N_NODES) ? g_cnt[i] : 0;
    if (i < N_NODES) g_dinv[i] = rsqrtf((float)v + 1.0f);  // +1 self-loop

    int x = v;
#pragma unroll
    for (int off = 1; off < 32; off <<= 1) {
        int y = __shfl_up_sync(0xFFFFFFFFu, x, off);
        if (lane >= off) x += y;
    }
    if (lane == 31) warpSums[warp] = x;
    __syncthreads();

    if (warp == 0) {
        int w = warpSums[lane];
#pragma unroll
        for (int off = 1; off < 32; off <<= 1) {
            int y = __shfl_up_sync(0xFFFFFFFFu, w, off);
            if (lane >= off) w += y;
        }
        warpSums[lane] = w;
    }
    __syncthreads();

    int incl = x + (warp > 0 ? warpSums[warp - 1] : 0);
    if (i < N_NODES) g_scan[i] = incl - v;   // exclusive within block
    if (t == SCAN_BLK - 1) g_bsum[blockIdx.x] = incl;
}

// merged scan2+scan3: every block redundantly scans the NB block sums in smem
__global__ void scan3_kernel() {
    __shared__ int sm[2][128];
    int t = threadIdx.x;
    if (t < 128) sm[0][t] = (t < NB) ? g_bsum[t] : 0;
    __syncthreads();
    int pi = 0;
#pragma unroll
    for (int off = 1; off < 128; off <<= 1) {
        if (t < 128) {
            int x = sm[pi][t];
            if (t >= off) x += sm[pi][t - off];
            sm[pi ^ 1][t] = x;
        }
        __syncthreads();
        pi ^= 1;
    }
    int i = blockIdx.x * blockDim.x + t;
    if (i < N_NODES) {
        int b = i >> 10;
        int base = (b > 0) ? sm[pi][b - 1] : 0;
        int r = g_scan[i] + base;
        g_rowptr[i] = r;
        g_cursor[i] = r;
    }
    if (i == 0) g_rowptr[N_NODES] = N_EDGES;
}

__global__ void fill_kernel(const int* __restrict__ src,
                            const int* __restrict__ dst) {
    int e = blockIdx.x * blockDim.x + threadIdx.x;
    if (e < N_EDGES) {
        int d = dst[e];
        int pos = atomicAdd(&g_cursor[d], 1);
        g_csr[pos] = src[e];
    }
}

// ------------------------------------------------------------- HMMA GEMM
// SCALE=true:  out = dinv[row] * (X@W)   (reads g_dinv in epilogue)
// SCALE=false: out = X@W                 (no dinv dependency at all)
template <int K, int M, int WS_STRIDE, bool CVT_A, bool SCALE, typename XT>
__global__ void __launch_bounds__(256) gemm_mma_kernel(
    const XT* __restrict__ X, const float* __restrict__ W,
    __half* __restrict__ out)
{
    constexpr int AS_STRIDE = K + 8;
    constexpr int NC = M / 8;
    __shared__ __align__(16) __half Asm[128 * AS_STRIDE];
    __shared__ __align__(16) __half Wsm[K * WS_STRIDE];

    const int tid = threadIdx.x;
    const int warp = tid >> 5;
    const int lane = tid & 31;
    const int rowBase = blockIdx.x * 128;

    if (CVT_A) {
        const float4* X4 = reinterpret_cast<const float4*>(X);
        constexpr int SEGS = K / 4;
        for (int idx = tid; idx < 128 * SEGS; idx += 256) {
            int rl = idx / SEGS;
            int seg = idx % SEGS;
            int row = rowBase + rl;
            float4 v = make_float4(0.f, 0.f, 0.f, 0.f);
            if (row < N_NODES) v = __ldg(&X4[(size_t)row * SEGS + seg]);
            __half2 h0 = __float22half2_rn(make_float2(v.x, v.y));
            __half2 h1 = __float22half2_rn(make_float2(v.z, v.w));
            uint2 p;
            p.x = *reinterpret_cast<unsigned*>(&h0);
            p.y = *reinterpret_cast<unsigned*>(&h1);
            *reinterpret_cast<uint2*>(&Asm[rl * AS_STRIDE + seg * 4]) = p;
        }
    } else {
        const uint4* X4 = reinterpret_cast<const uint4*>(X);
        constexpr int SEGS = K / 8;
        for (int idx = tid; idx < 128 * SEGS; idx += 256) {
            int rl = idx / SEGS;
            int seg = idx % SEGS;
            int row = rowBase + rl;
            uint4 v = make_uint4(0u, 0u, 0u, 0u);
            if (row < N_NODES) v = __ldg(&X4[(size_t)row * SEGS + seg]);
            *reinterpret_cast<uint4*>(&Asm[rl * AS_STRIDE + seg * 8]) = v;
        }
    }
    for (int idx = tid; idx < K * M; idx += 256) {
        int k = idx / M;
        int m = idx % M;
        Wsm[k * WS_STRIDE + m] = __float2half(__ldg(&W[idx]));
    }
    __syncthreads();

    float acc[NC][4];
#pragma unroll
    for (int n = 0; n < NC; n++)
#pragma unroll
        for (int q = 0; q < 4; q++) acc[n][q] = 0.f;

    const unsigned aBase = (unsigned)__cvta_generic_to_shared(Asm);
    const unsigned wBase = (unsigned)__cvta_generic_to_shared(Wsm);
    const int rlane = lane & 15;
    const int hilo = lane >> 4;

#pragma unroll
    for (int k0 = 0; k0 < K; k0 += 16) {
        unsigned a0, a1, a2, a3;
        unsigned aAddr = aBase +
            ((warp * 16 + rlane) * AS_STRIDE + k0) * 2 + hilo * 16;
        asm volatile("ldmatrix.sync.aligned.m8n8.x4.shared.b16 {%0,%1,%2,%3}, [%4];"
                     : "=r"(a0), "=r"(a1), "=r"(a2), "=r"(a3) : "r"(aAddr));
#pragma unroll
        for (int n = 0; n < NC; n++) {
            unsigned b0, b1;
            unsigned bAddr = wBase + ((k0 + rlane) * WS_STRIDE + n * 8) * 2;
            asm volatile("ldmatrix.sync.aligned.m8n8.x2.trans.shared.b16 {%0,%1}, [%2];"
                         : "=r"(b0), "=r"(b1) : "r"(bAddr));
            asm volatile(
                "mma.sync.aligned.m16n8k16.row.col.f32.f16.f16.f32 "
                "{%0,%1,%2,%3}, {%4,%5,%6,%7}, {%8,%9}, {%0,%1,%2,%3};"
                : "+f"(acc[n][0]), "+f"(acc[n][1]), "+f"(acc[n][2]), "+f"(acc[n][3])
                : "r"(a0), "r"(a1), "r"(a2), "r"(a3), "r"(b0), "r"(b1));
        }
    }

    int row0 = rowBase + warp * 16 + (lane >> 2);
    int row1 = row0 + 8;
    float s0 = 1.f, s1 = 1.f;
    if (SCALE) {
        s0 = (row0 < N_NODES) ? g_dinv[row0] : 0.f;
        s1 = (row1 < N_NODES) ? g_dinv[row1] : 0.f;
    }
    unsigned* outU = reinterpret_cast<unsigned*>(out);
#pragma unroll
    for (int n = 0; n < NC; n++) {
        int col = n * 8 + (lane & 3) * 2;
        if (row0 < N_NODES) {
            __half2 h = __float22half2_rn(make_float2(acc[n][0] * s0, acc[n][1] * s0));
            outU[((size_t)row0 * M + col) >> 1] = *reinterpret_cast<unsigned*>(&h);
        }
        if (row1 < N_NODES) {
            __half2 h = __float22half2_rn(make_float2(acc[n][2] * s1, acc[n][3] * s1));
            outU[((size_t)row1 * M + col) >> 1] = *reinterpret_cast<unsigned*>(&h);
        }
    }
}

// ------------------------------------------------------- fused gather
struct F8 { float v[8]; };
__device__ __forceinline__ void acc8(F8& a, uint4 p) {
    const __half2* h = reinterpret_cast<const __half2*>(&p);
#pragma unroll
    for (int q = 0; q < 4; q++) {
        float2 f = __half22float2(h[q]);
        a.v[2 * q]     += f.x;
        a.v[2 * q + 1] += f.y;
    }
}
__device__ __forceinline__ void acc8s(F8& a, uint4 p, float s) {
    const __half2* h = reinterpret_cast<const __half2*>(&p);
#pragma unroll
    for (int q = 0; q < 4; q++) {
        float2 f = __half22float2(h[q]);
        a.v[2 * q]     = fmaf(s, f.x, a.v[2 * q]);
        a.v[2 * q + 1] = fmaf(s, f.y, a.v[2 * q + 1]);
    }
}

// SRC_SCALED=false: g holds unscaled XW; scale each source row by dinv[src].
// 8 threads/row, 8 features/thread, 2 chains (proven shape).
template <bool SRC_SCALED>
__global__ void gather_relu64_kernel(const uint4* __restrict__ g,
                                     const float* __restrict__ bias,
                                     uint4* __restrict__ Ch)
{
    int tid = blockIdx.x * blockDim.x + threadIdx.x;
    int row = tid >> 3;
    int j = tid & 7;
    if (row >= N_NODES) return;
    int beg = g_rowptr[row], end = g_rowptr[row + 1];

    F8 a0, a1;
#pragma unroll
    for (int q = 0; q < 8; q++) { a0.v[q] = 0.f; a1.v[q] = 0.f; }

    int e = beg;
    for (; e + 1 < end; e += 2) {
        int s0 = __ldg(&g_csr[e]);
        int s1 = __ldg(&g_csr[e + 1]);
        if (SRC_SCALED) {
            acc8(a0, __ldg(&g[(size_t)s0 * 8 + j]));
            acc8(a1, __ldg(&g[(size_t)s1 * 8 + j]));
        } else {
            float d0 = __ldg(&g_dinv[s0]);
            float d1 = __ldg(&g_dinv[s1]);
            acc8s(a0, __ldg(&g[(size_t)s0 * 8 + j]), d0);
            acc8s(a1, __ldg(&g[(size_t)s1 * 8 + j]), d1);
        }
    }
    if (e < end) {
        int s = __ldg(&g_csr[e]);
        if (SRC_SCALED) acc8(a0, __ldg(&g[(size_t)s * 8 + j]));
        else            acc8s(a0, __ldg(&g[(size_t)s * 8 + j]), __ldg(&g_dinv[s]));
    }
    float sr = g_dinv[row];
    if (SRC_SCALED) acc8(a0, __ldg(&g[(size_t)row * 8 + j]));       // self
    else            acc8s(a0, __ldg(&g[(size_t)row * 8 + j]), sr);  // self
#pragma unroll
    for (int q = 0; q < 8; q++) a0.v[q] += a1.v[q];

    const float4* b4 = reinterpret_cast<const float4*>(bias);
    float4 bb0 = __ldg(&b4[2 * j]);
    float4 bb1 = __ldg(&b4[2 * j + 1]);
    float r0 = fmaxf(fmaf(sr, a0.v[0], bb0.x), 0.f);
    float r1 = fmaxf(fmaf(sr, a0.v[1], bb0.y), 0.f);
    float r2 = fmaxf(fmaf(sr, a0.v[2], bb0.z), 0.f);
    float r3 = fmaxf(fmaf(sr, a0.v[3], bb0.w), 0.f);
    float r4 = fmaxf(fmaf(sr, a0.v[4], bb1.x), 0.f);
    float r5 = fmaxf(fmaf(sr, a0.v[5], bb1.y), 0.f);
    float r6 = fmaxf(fmaf(sr, a0.v[6], bb1.z), 0.f);
    float r7 = fmaxf(fmaf(sr, a0.v[7], bb1.w), 0.f);
    __half2 h0 = __float22half2_rn(make_float2(r0, r1));
    __half2 h1 = __float22half2_rn(make_float2(r2, r3));
    __half2 h2 = __float22half2_rn(make_float2(r4, r5));
    __half2 h3 = __float22half2_rn(make_float2(r6, r7));
    uint4 o;
    o.x = *reinterpret_cast<unsigned*>(&h0);
    o.y = *reinterpret_cast<unsigned*>(&h1);
    o.z = *reinterpret_cast<unsigned*>(&h2);
    o.w = *reinterpret_cast<unsigned*>(&h3);
    Ch[(size_t)row * 8 + j] = o;
}

// ---- fused: gather 40-wide logits + bias + log_softmax -> final output ----
// 10 threads/row (proven gather shape), 32 rows per 320-thread block.
// 100000*10/320 = 3125 blocks exactly — no tail, no idle lanes.
// Softmax reduction over each row's 10 threads via shared memory.
// Also re-zeroes g_cnt for the next invocation.
__global__ void __launch_bounds__(320) gather_lsm40_kernel(
    const uint2* __restrict__ g, const float* __restrict__ b3,
    float* __restrict__ out)
{
    __shared__ float smax[32][10];
    __shared__ float ssum[32][10];

    int t = threadIdx.x;
    int rl = t / 10;
    int j = t - rl * 10;
    int row = blockIdx.x * 32 + rl;

    // re-zero g_cnt (1M threads cover N_NODES)
    int gtid = blockIdx.x * 320 + t;
    if (gtid < N_NODES) g_cnt[gtid] = 0;

    int beg = g_rowptr[row], end = g_rowptr[row + 1];

    float a0 = 0.f, a1 = 0.f, a2 = 0.f, a3 = 0.f;
    for (int e = beg; e < end; e++) {
        int s = __ldg(&g_csr[e]);
        uint2 p = __ldg(&g[(size_t)s * 10 + j]);
        float2 f0 = __half22float2(*reinterpret_cast<const __half2*>(&p.x));
        float2 f1 = __half22float2(*reinterpret_cast<const __half2*>(&p.y));
        a0 += f0.x; a1 += f0.y; a2 += f1.x; a3 += f1.y;
    }
    {
        uint2 p = __ldg(&g[(size_t)row * 10 + j]);   // self loop
        float2 f0 = __half22float2(*reinterpret_cast<const __half2*>(&p.x));
        float2 f1 = __half22float2(*reinterpret_cast<const __half2*>(&p.y));
        a0 += f0.x; a1 += f0.y; a2 += f1.x; a3 += f1.y;
    }
    float s = g_dinv[row];
    float4 bb = __ldg(&reinterpret_cast<const float4*>(b3)[j]);
    a0 = fmaf(s, a0, bb.x);
    a1 = fmaf(s, a1, bb.y);
    a2 = fmaf(s, a2, bb.z);
    a3 = fmaf(s, a3, bb.w);

    // row max across 10 threads
    smax[rl][j] = fmaxf(fmaxf(a0, a1), fmaxf(a2, a3));
    __syncthreads();
    float m = smax[rl][0];
#pragma unroll
    for (int k = 1; k < 10; k++) m = fmaxf(m, smax[rl][k]);

    // row exp-sum across 10 threads
    ssum[rl][j] = __expf(a0 - m) + __expf(a1 - m) + __expf(a2 - m) + __expf(a3 - m);
    __syncthreads();
    float sum = ssum[rl][0];
#pragma unroll
    for (int k = 1; k < 10; k++) sum += ssum[rl][k];

    float ls = m + __logf(sum);
    float4 r = make_float4(a0 - ls, a1 - ls, a2 - ls, a3 - ls);
    reinterpret_cast<float4*>(out)[(size_t)row * 10 + j] = r;
}

// ------------------------------------------------------------------ launch
extern "C" void kernel_launch(void* const* d_in, const int* in_sizes, int n_in,
                              void* d_out, int out_size)
{
    const float* x   = (const float*)d_in[0];
    const int* ei    = (const int*)d_in[1];
    const float* W1  = (const float*)d_in[2];
    const float* b1  = (const float*)d_in[3];
    const float* W2  = (const float*)d_in[4];
    const float* b2  = (const float*)d_in[5];
    const float* W3  = (const float*)d_in[6];
    const float* b3  = (const float*)d_in[7];
    float* out       = (float*)d_out;

    const int* src = ei;
    const int* dst = ei + N_EDGES;

    __half* Ah; cudaGetSymbolAddress((void**)&Ah, g_Ah);
    __half* Ch; cudaGetSymbolAddress((void**)&Ch, g_Ch);

    const int TPB = 256;
    const int nodeBlocks = (N_NODES + TPB - 1) / TPB;
    const int edgeBlocks = (N_EDGES + TPB - 1) / TPB;
    const int mma_blocks = (N_NODES + 127) / 128;
    const int g64_blocks = (N_NODES * 8 + TPB - 1) / TPB;
    const int g40_blocks = N_NODES * 10 / 320;   // 3125 exact

    cudaStream_t s2;
    cudaStreamCreateWithFlags(&s2, cudaStreamNonBlocking);
    cudaEvent_t evA, evB;
    cudaEventCreateWithFlags(&evA, cudaEventDisableTiming);
    cudaEventCreateWithFlags(&evB, cudaEventDisableTiming);

    // fork at t=0: gemm1 (unscaled) depends only on x, W1
    cudaEventRecord(evA, 0);
    cudaStreamWaitEvent(s2, evA, 0);
    gemm_mma_kernel<NFEAT, NHID, NHID + 8, true, false>
        <<<mma_blocks, 256, 0, s2>>>(x, W1, Ah);

    // main stream: entire CSR build, concurrent with gemm1
    // (g_cnt was zeroed by the previous invocation's gather_lsm40_kernel,
    //  or is zero-initialized on the very first call)
    hist_kernel<<<edgeBlocks, TPB>>>(dst);
    scan1_kernel<<<NB, SCAN_BLK>>>();          // also produces dinv
    scan3_kernel<<<nodeBlocks, TPB>>>();
    fill_kernel<<<edgeBlocks, TPB>>>(src, dst);

    // join: gather1 needs CSR + dinv + gemm1 output
    cudaEventRecord(evB, s2);
    cudaStreamWaitEvent(0, evB, 0);

    // ---- layer 1 aggregation (applies dinv[src] on the fly) ----
    gather_relu64_kernel<false><<<g64_blocks, TPB>>>((const uint4*)Ah, b1, (uint4*)Ch);

    // ---- layer 2 ----
    gemm_mma_kernel<NHID, NHID, NHID + 8, false, true><<<mma_blocks, 256>>>(Ch, W2, Ah);
    gather_relu64_kernel<true><<<g64_blocks, TPB>>>((const uint4*)Ah, b2, (uint4*)Ch);

    // ---- layer 3 ----
    gemm_mma_kernel<NHID, NCLASS, NCLASS + 16, false, true><<<mma_blocks, 256>>>(Ch, W3, Ah);
    gather_lsm40_kernel<<<g40_blocks, 320>>>((const uint2*)Ah, b3, out);
}